// round 14
// baseline (speedup 1.0000x reference)
#include <cuda_runtime.h>
#include <cstdint>

// Gini of n=8192 fp32, single launch, 128 blocks (one wave, 1 block/SM).
//
// Closed form vs a SORTED strip c_0<=..<=c_{S-1} (prefix P, p = #{c < r}):
//    sum_c |r-c| = r*(2p - S) + T - 2*P[p]     (exact, ties cancel)
//
// 32 strips of 256. Block (rc, g): rows rc*256..+255 vs strip group g
// (8 strips). Sorts its 8 strips SIMULTANEOUSLY (1 elem/thread/strip,
// register bitonic: shfl_xor for j<=16, smem for j>=32 -> only 6 smem
// phases of 36). Then each thread: 8 interleaved 8-step binary searches.
// Blocks rc==0 also emit per-group min/sum from sorted data.
// Sum over full n x n (diagonal contributes 0) => no symmetry factor.

#define THREADS  256
#define SSIZE    256          // strip length
#define SPB      8            // strips per block
#define GROUPS   4            // strip groups (SPB*GROUPS*SSIZE = 8192)
#define RCHUNKS  32           // row chunks of 256
#define NBLK     (RCHUNKS * GROUPS)   // 128
#define PITCH    257
#define GEN_MAX  4096

__device__ float        g_part[NBLK > GEN_MAX ? NBLK : GEN_MAX];
__device__ float        g_gmin[GROUPS];
__device__ float        g_gsum[GROUPS];
__device__ float        g_min_val;   // used by generic fallback
__device__ float        g_sum_val;
__device__ unsigned int g_count = 0;

__device__ __forceinline__ float warp_sum(float v) {
#pragma unroll
    for (int off = 16; off > 0; off >>= 1)
        v += __shfl_xor_sync(0xFFFFFFFFu, v, off);
    return v;
}

// ---------------- main kernel (n == 8192) ----------------
__global__ __launch_bounds__(THREADS)
void k_gini(const float* __restrict__ x, float* __restrict__ out, int n) {
    __shared__ float sval[SPB * PITCH];     // sorted values (also sort exchange)
    __shared__ float spre[SPB * PITCH];     // exclusive prefix sums
    __shared__ float wt[SPB][8];            // per-warp scan totals
    __shared__ float sT[SPB];               // strip totals
    __shared__ float red[THREADS / 32];
    __shared__ unsigned int isLast;

    const int tid = threadIdx.x;
    const int b   = blockIdx.x;
    const int g   = b & (GROUPS - 1);       // strip group
    const int rc  = b >> 2;                 // row chunk
    const int colBase = g * (SPB * SSIZE);

    // loads: one row element + 8 strip elements (all coalesced)
    const float r = x[rc * THREADS + tid];
    float v[SPB];
#pragma unroll
    for (int s = 0; s < SPB; ++s)
        v[s] = x[colBase + s * SSIZE + tid];

    // ---- bitonic sort of 8 strips simultaneously (ascending) ----
    // thread tid owns position tid of every strip.
#pragma unroll
    for (int k = 2; k <= SSIZE; k <<= 1) {
#pragma unroll
        for (int j = k >> 1; j > 0; j >>= 1) {
            const bool take_min = (((tid & j) == 0) == ((tid & k) == 0));
            if (j >= 32) {
#pragma unroll
                for (int s = 0; s < SPB; ++s) sval[s * PITCH + tid] = v[s];
                __syncthreads();
#pragma unroll
                for (int s = 0; s < SPB; ++s) {
                    float w = sval[s * PITCH + (tid ^ j)];
                    v[s] = take_min ? fminf(v[s], w) : fmaxf(v[s], w);
                }
                __syncthreads();
            } else {
#pragma unroll
                for (int s = 0; s < SPB; ++s) {
                    float w = __shfl_xor_sync(0xFFFFFFFFu, v[s], j);
                    v[s] = take_min ? fminf(v[s], w) : fmaxf(v[s], w);
                }
            }
        }
    }

    // ---- exclusive prefix sums per strip (warp scan + carries) ----
    const int lane = tid & 31;
    const int wid  = tid >> 5;
    float inc[SPB];
#pragma unroll
    for (int s = 0; s < SPB; ++s) {
        float e = v[s];
#pragma unroll
        for (int off = 1; off < 32; off <<= 1) {
            float o = __shfl_up_sync(0xFFFFFFFFu, e, off);
            if (lane >= off) e += o;
        }
        inc[s] = e;                          // inclusive within warp
        if (lane == 31) wt[s][wid] = e;      // warp total
    }
    __syncthreads();
#pragma unroll
    for (int s = 0; s < SPB; ++s) {
        float carry = 0.0f;
#pragma unroll
        for (int w = 0; w < 8; ++w)
            if (w < wid) carry += wt[s][w];
        sval[s * PITCH + tid] = v[s];
        spre[s * PITCH + tid] = carry + inc[s] - v[s];   // exclusive
    }
    if (tid < SPB) {
        float t = 0.0f;
#pragma unroll
        for (int w = 0; w < 8; ++w) t += wt[tid][w];
        sT[tid] = t;
        spre[tid * PITCH + SSIZE] = t;       // P[S] = T  (p==S lookup)
    }
    __syncthreads();

    // blocks of row-chunk 0 emit per-group min & sum (from sorted strips)
    if (rc == 0 && tid == 0) {
        float mn = sval[0];
        float sm = 0.0f;
#pragma unroll
        for (int s = 0; s < SPB; ++s) {
            mn = fminf(mn, sval[s * PITCH]);
            sm += sT[s];
        }
        g_gmin[g] = mn;
        g_gsum[g] = sm;
    }

    // ---- 8 interleaved branchless binary searches (lower_bound) ----
    int lo[SPB], hi[SPB];
#pragma unroll
    for (int s = 0; s < SPB; ++s) { lo[s] = 0; hi[s] = SSIZE; }
#pragma unroll
    for (int it = 0; it < 8; ++it) {
#pragma unroll
        for (int s = 0; s < SPB; ++s) {
            int m = (lo[s] + hi[s]) >> 1;
            bool lt = sval[s * PITCH + m] < r;
            lo[s] = lt ? m + 1 : lo[s];
            hi[s] = lt ? hi[s] : m;
        }
    }
    int   sump = 0;
    float sumP = 0.0f, TT = 0.0f;
#pragma unroll
    for (int s = 0; s < SPB; ++s) {
        sump += lo[s];
        sumP += spre[s * PITCH + lo[s]];
        TT   += sT[s];
    }
    float part = r * (float)(2 * sump - SPB * SSIZE) + TT - 2.0f * sumP;

    // ---- block reduce -> partial, last block finalizes ----
    part = warp_sum(part);
    if ((tid & 31) == 0) red[wid] = part;
    __syncthreads();
    if (tid == 0) {
        float p = 0.0f;
#pragma unroll
        for (int w = 0; w < THREADS / 32; ++w) p += red[w];
        g_part[b] = p;
        __threadfence();
        unsigned int c = atomicAdd(&g_count, 1u);
        isLast = (c == gridDim.x - 1) ? 1u : 0u;
    }
    __syncthreads();

    if (isLast) {
        __threadfence();
        // fixed-order reduce of 128 partials
        float s = 0.0f;
        for (int i = tid; i < NBLK; i += THREADS) s += g_part[i];
        s = warp_sum(s);
        if ((tid & 31) == 0) red[wid] = s;
        __syncthreads();
        if (tid == 0) {
            float S = 0.0f;
#pragma unroll
            for (int w = 0; w < THREADS / 32; ++w) S += red[w];
            float mn = g_gmin[0], sm = g_gsum[0];
#pragma unroll
            for (int q = 1; q < GROUPS; ++q) {
                mn = fminf(mn, g_gmin[q]);
                sm += g_gsum[q];
            }
            const float nf = (float)n;
            float mean = sm / nf;
            if (mn < 0.0f) mean -= mn;        // mean(x - min)
            out[0] = S / (2.0f * nf * nf * (mean + 1e-8f));
            g_count = 0;                       // reset for graph replay
        }
    }
}

// ---------------- generic fallback (any n) ----------------
__global__ void k_gini_generic(const float* __restrict__ x, float* __restrict__ out, int n) {
    __shared__ float red[THREADS];
    __shared__ float smin[THREADS];
    __shared__ unsigned int isLast;
    const int tid = threadIdx.x;
    const int i = blockIdx.x * THREADS + tid;
    float a = 0.0f;
    if (i < n) {
        const float xi = x[i];
        for (int j = 0; j < n; ++j) a += fabsf(xi - x[j]);
    }
    red[tid] = a;
    __syncthreads();
    for (int off = THREADS / 2; off > 0; off >>= 1) {
        if (tid < off) red[tid] += red[tid + off];
        __syncthreads();
    }
    if (tid == 0) {
        g_part[blockIdx.x] = red[0];
        __threadfence();
        unsigned int c = atomicAdd(&g_count, 1u);
        isLast = (c == gridDim.x - 1) ? 1u : 0u;
    }
    __syncthreads();
    if (isLast) {
        __threadfence();
        float mn = 3.402823466e38f, sm = 0.0f;
        for (int k = tid; k < n; k += THREADS) {
            float v = x[k];
            mn = fminf(mn, v);
            sm += v;
        }
        red[tid] = sm; smin[tid] = mn;
        __syncthreads();
        for (int off = THREADS / 2; off > 0; off >>= 1) {
            if (tid < off) {
                red[tid] += red[tid + off];
                smin[tid] = fminf(smin[tid], smin[tid + off]);
            }
            __syncthreads();
        }
        if (tid == 0) { g_min_val = smin[0]; g_sum_val = red[0]; }
        __syncthreads();
        float s = 0.0f;
        for (int k = tid; k < gridDim.x; k += THREADS) s += g_part[k];
        red[tid] = s;
        __syncthreads();
        for (int off = THREADS / 2; off > 0; off >>= 1) {
            if (tid < off) red[tid] += red[tid + off];
            __syncthreads();
        }
        if (tid == 0) {
            const float nf = (float)n;
            float mean = g_sum_val / nf;
            if (g_min_val < 0.0f) mean -= g_min_val;
            out[0] = red[0] / (2.0f * nf * nf * (mean + 1e-8f));
            g_count = 0;
        }
    }
}

extern "C" void kernel_launch(void* const* d_in, const int* in_sizes, int n_in,
                              void* d_out, int out_size) {
    const float* x = (const float*)d_in[0];
    float* out = (float*)d_out;
    const int n = in_sizes[0];

    if (n == RCHUNKS * THREADS) {             // 8192
        k_gini<<<NBLK, THREADS>>>(x, out, n);
    } else {
        int nblk = (n + THREADS - 1) / THREADS;
        if (nblk > GEN_MAX) nblk = GEN_MAX;
        k_gini_generic<<<nblk, THREADS>>>(x, out, n);
    }
}

// round 17
// speedup vs baseline: 1.0299x; 1.0299x over previous
#include <cuda_runtime.h>
#include <cstdint>

// Gini of n=8192 fp32, single launch, 256 blocks.
//
// Closed form vs a SORTED strip c_0<=..<=c_{S-1} (prefix P, p = #{c < r}):
//    sum_c |r-c| = r*(2p - S) + T - 2*P[p]     (exact, ties cancel)
//
// 64 strips of 128 (S=128 => 28 bitonic phases, only 3 need smem).
// Block (rc, g): 256 rows vs strip group g (8 strips). Thread layout for
// the sort: position = tid & 127, half = tid >> 7 => 4 strips per thread,
// shfl exchanges for j<=16, smem for j in {32, 64}. One warp scans one
// strip's prefix sums (no block barriers). Search: 8 x 7-step interleaved
// branchless lower_bounds per row. rc==0 blocks emit per-group min/sum.
// Full n x n sum (diagonal = 0) => no symmetry factor. Deterministic.

#define THREADS  256
#define SSIZE    128
#define SPB      8
#define GROUPS   8            // SPB*GROUPS*SSIZE = 8192
#define RCHUNKS  32           // row chunks of 256
#define NBLK     (RCHUNKS * GROUPS)   // 256
#define PITCH    129
#define GEN_MAX  4096

__device__ float        g_part[NBLK > GEN_MAX ? NBLK : GEN_MAX];
__device__ float        g_gmin[GROUPS];
__device__ float        g_gsum[GROUPS];
__device__ float        g_min_val;   // generic fallback
__device__ float        g_sum_val;
__device__ unsigned int g_count = 0;

__device__ __forceinline__ float warp_sum(float v) {
#pragma unroll
    for (int off = 16; off > 0; off >>= 1)
        v += __shfl_xor_sync(0xFFFFFFFFu, v, off);
    return v;
}

// ---------------- main kernel (n == 8192) ----------------
__global__ __launch_bounds__(THREADS)
void k_gini(const float* __restrict__ x, float* __restrict__ out, int n) {
    __shared__ float sval[SPB * PITCH];     // sorted values / sort exchange
    __shared__ float spre[SPB * PITCH];     // exclusive prefix sums (+T at [S])
    __shared__ float sT[SPB];               // strip totals
    __shared__ float red[THREADS / 32];
    __shared__ unsigned int isLast;

    const int tid  = threadIdx.x;
    const int b    = blockIdx.x;
    const int g    = b & (GROUPS - 1);
    const int rc   = b >> 3;
    const int pos  = tid & (SSIZE - 1);     // position within strip
    const int half = tid >> 7;              // 0: strips 0-3, 1: strips 4-7
    const int colBase = g * (SPB * SSIZE);

    // loads: one row element + 4 strip elements per thread (coalesced)
    const float r = x[rc * THREADS + tid];
    float v[4];
#pragma unroll
    for (int q = 0; q < 4; ++q)
        v[q] = x[colBase + (half * 4 + q) * SSIZE + pos];

    // ---- bitonic sort of 8 strips simultaneously (ascending by pos) ----
#pragma unroll
    for (int k = 2; k <= SSIZE; k <<= 1) {
#pragma unroll
        for (int j = k >> 1; j > 0; j >>= 1) {
            const bool take_min = (((pos & j) == 0) == ((pos & k) == 0));
            if (j >= 32) {                  // cross-warp: via smem (3 phases total)
#pragma unroll
                for (int q = 0; q < 4; ++q)
                    sval[(half * 4 + q) * PITCH + pos] = v[q];
                __syncthreads();
#pragma unroll
                for (int q = 0; q < 4; ++q) {
                    float w = sval[(half * 4 + q) * PITCH + (pos ^ j)];
                    v[q] = take_min ? fminf(v[q], w) : fmaxf(v[q], w);
                }
                __syncthreads();
            } else {                        // intra-warp: shfl (25 phases)
#pragma unroll
                for (int q = 0; q < 4; ++q) {
                    float w = __shfl_xor_sync(0xFFFFFFFFu, v[q], j);
                    v[q] = take_min ? fminf(v[q], w) : fmaxf(v[q], w);
                }
            }
        }
    }
#pragma unroll
    for (int q = 0; q < 4; ++q)
        sval[(half * 4 + q) * PITCH + pos] = v[q];
    __syncthreads();

    // ---- prefix sums: one warp per strip (8 warps, 8 strips) ----
    {
        const int w = tid >> 5;             // warp id == strip id
        const int l = tid & 31;
        const float* src = sval + w * PITCH;
        float e0 = src[4 * l];
        float e1 = e0 + src[4 * l + 1];
        float e2 = e1 + src[4 * l + 2];
        float e3 = e2 + src[4 * l + 3];
        float e = e3;
#pragma unroll
        for (int off = 1; off < 32; off <<= 1) {
            float o = __shfl_up_sync(0xFFFFFFFFu, e, off);
            if (l >= off) e += o;
        }
        float exc = e - e3;                 // exclusive carry for this lane
        float* dst = spre + w * PITCH;
        dst[4 * l]     = exc;
        dst[4 * l + 1] = exc + e0;
        dst[4 * l + 2] = exc + e1;
        dst[4 * l + 3] = exc + e2;
        if (l == 31) {
            float T = exc + e3;
            dst[SSIZE] = T;                 // P[S] = T
            sT[w] = T;
        }
    }
    __syncthreads();

    // rc==0 blocks: per-group min & sum from sorted data
    if (rc == 0 && tid == 0) {
        float mn = sval[0];
        float sm = 0.0f;
#pragma unroll
        for (int s = 0; s < SPB; ++s) {
            mn = fminf(mn, sval[s * PITCH]);
            sm += sT[s];
        }
        g_gmin[g] = mn;
        g_gsum[g] = sm;
    }

    // ---- 8 interleaved branchless binary searches (lower_bound) ----
    int lo[SPB];
#pragma unroll
    for (int s = 0; s < SPB; ++s) lo[s] = 0;
    int hi[SPB];
#pragma unroll
    for (int s = 0; s < SPB; ++s) hi[s] = SSIZE;
#pragma unroll
    for (int it = 0; it < 7; ++it) {
#pragma unroll
        for (int s = 0; s < SPB; ++s) {
            int m = (lo[s] + hi[s]) >> 1;
            bool lt = sval[s * PITCH + m] < r;
            lo[s] = lt ? m + 1 : lo[s];
            hi[s] = lt ? hi[s] : m;
        }
    }
    int   sump = 0;
    float sumP = 0.0f, TT = 0.0f;
#pragma unroll
    for (int s = 0; s < SPB; ++s) {
        sump += lo[s];
        sumP += spre[s * PITCH + lo[s]];
        TT   += sT[s];
    }
    float part = r * (float)(2 * sump - SPB * SSIZE) + TT - 2.0f * sumP;

    // ---- block reduce -> partial, last block finalizes ----
    part = warp_sum(part);
    if ((tid & 31) == 0) red[tid >> 5] = part;
    __syncthreads();
    if (tid == 0) {
        float p = 0.0f;
#pragma unroll
        for (int w = 0; w < THREADS / 32; ++w) p += red[w];
        g_part[b] = p;
        __threadfence();
        unsigned int c = atomicAdd(&g_count, 1u);
        isLast = (c == gridDim.x - 1) ? 1u : 0u;
    }
    __syncthreads();

    if (isLast) {
        __threadfence();
        float s = 0.0f;
        for (int i = tid; i < NBLK; i += THREADS) s += g_part[i];
        s = warp_sum(s);
        if ((tid & 31) == 0) red[tid >> 5] = s;
        __syncthreads();
        if (tid == 0) {
            float S = 0.0f;
#pragma unroll
            for (int w = 0; w < THREADS / 32; ++w) S += red[w];
            float mn = g_gmin[0], sm = g_gsum[0];
#pragma unroll
            for (int q = 1; q < GROUPS; ++q) {
                mn = fminf(mn, g_gmin[q]);
                sm += g_gsum[q];
            }
            const float nf = (float)n;
            float mean = sm / nf;
            if (mn < 0.0f) mean -= mn;        // mean(x - min)
            out[0] = S / (2.0f * nf * nf * (mean + 1e-8f));
            g_count = 0;                       // reset for graph replay
        }
    }
}

// ---------------- generic fallback (any n) ----------------
__global__ void k_gini_generic(const float* __restrict__ x, float* __restrict__ out, int n) {
    __shared__ float red[THREADS];
    __shared__ float smin[THREADS];
    __shared__ unsigned int isLast;
    const int tid = threadIdx.x;
    const int i = blockIdx.x * THREADS + tid;
    float a = 0.0f;
    if (i < n) {
        const float xi = x[i];
        for (int j = 0; j < n; ++j) a += fabsf(xi - x[j]);
    }
    red[tid] = a;
    __syncthreads();
    for (int off = THREADS / 2; off > 0; off >>= 1) {
        if (tid < off) red[tid] += red[tid + off];
        __syncthreads();
    }
    if (tid == 0) {
        g_part[blockIdx.x] = red[0];
        __threadfence();
        unsigned int c = atomicAdd(&g_count, 1u);
        isLast = (c == gridDim.x - 1) ? 1u : 0u;
    }
    __syncthreads();
    if (isLast) {
        __threadfence();
        float mn = 3.402823466e38f, sm = 0.0f;
        for (int k = tid; k < n; k += THREADS) {
            float v = x[k];
            mn = fminf(mn, v);
            sm += v;
        }
        red[tid] = sm; smin[tid] = mn;
        __syncthreads();
        for (int off = THREADS / 2; off > 0; off >>= 1) {
            if (tid < off) {
                red[tid] += red[tid + off];
                smin[tid] = fminf(smin[tid], smin[tid + off]);
            }
            __syncthreads();
        }
        if (tid == 0) { g_min_val = smin[0]; g_sum_val = red[0]; }
        __syncthreads();
        float s = 0.0f;
        for (int k = tid; k < gridDim.x; k += THREADS) s += g_part[k];
        red[tid] = s;
        __syncthreads();
        for (int off = THREADS / 2; off > 0; off >>= 1) {
            if (tid < off) red[tid] += red[tid + off];
            __syncthreads();
        }
        if (tid == 0) {
            const float nf = (float)n;
            float mean = g_sum_val / nf;
            if (g_min_val < 0.0f) mean -= g_min_val;
            out[0] = red[0] / (2.0f * nf * nf * (mean + 1e-8f));
            g_count = 0;
        }
    }
}

extern "C" void kernel_launch(void* const* d_in, const int* in_sizes, int n_in,
                              void* d_out, int out_size) {
    const float* x = (const float*)d_in[0];
    float* out = (float*)d_out;
    const int n = in_sizes[0];

    if (n == RCHUNKS * THREADS) {             // 8192
        k_gini<<<NBLK, THREADS>>>(x, out, n);
    } else {
        int nblk = (n + THREADS - 1) / THREADS;
        if (nblk > GEN_MAX) nblk = GEN_MAX;
        k_gini_generic<<<nblk, THREADS>>>(x, out, n);
    }
}